// round 17
// baseline (speedup 1.0000x reference)
#include <cuda_runtime.h>
#include <math.h>

// Problem constants
#define BQ 8
#define TT 2048
#define DD 512
#define SDIM 256
#define ODIM 64
#define MM (BQ*TT)          // 16384 rows
#define N1 768              // padded 704 (gate 0-255 | in 256-511 | v 512-575 | k 576-639 | q 640-703)
#define KC2 320             // states(256) + bind(64)
#define NCH 64              // scan chunks of 32
#define CHK 32
#define CB 64               // binding chunk
#define NCB 32

// ---------------- device scratch (no runtime allocation) ----------------
__device__ float g_W1[DD*N1];
__device__ float g_b1[N1];
__device__ float g_Z[(size_t)MM*N1];
__device__ float g_W2[KC2*DD];
__device__ float g_b2[DD];
__device__ float g_A2[(size_t)MM*KC2];    // written pre-rounded to tf32
__device__ float g_Y[(size_t)MM*DD];
__device__ float2 g_sumAB[BQ*NCH*SDIM];   // {1/rca, wb} pairs
__device__ float g_hpr[BQ*NCH*SDIM];
__device__ float g_Mc[(size_t)BQ*NCB*ODIM*ODIM];
__device__ float g_Sc[(size_t)BQ*NCB*ODIM*ODIM];
__device__ float g_pw[65*ODIM];

__device__ __forceinline__ float sigm_acc(float z){ return 1.0f/(1.0f+expf(-z)); }

__device__ __forceinline__ unsigned f2tf(float x){
    unsigned r; asm("cvt.rna.tf32.f32 %0, %1;" : "=r"(r) : "f"(x)); return r;
}
__device__ __forceinline__ float tfr(float x){ return __uint_as_float(f2tf(x)); }

// ---------------- fused prep kernel ----------------
// blocks [0,1536): W1; [1536,2176): W2; 2176: pw
__global__ void pack_all(const float* __restrict__ gW, const float* __restrict__ gb,
                         const float* __restrict__ iW, const float* __restrict__ ib,
                         const float* __restrict__ vW, const float* __restrict__ vb,
                         const float* __restrict__ kW, const float* __restrict__ kb,
                         const float* __restrict__ qW, const float* __restrict__ qb,
                         const float* __restrict__ oW, const float* __restrict__ ob,
                         const float* __restrict__ pW, const float* __restrict__ pb,
                         const float* __restrict__ op_decay)
{
    int bid = blockIdx.x;
    if (bid < 1536) {
        int idx = bid*256 + threadIdx.x;
        int d = idx / N1, n = idx % N1;
        float w = 0.f;
        if      (n < 256) w = gW[d*256 + n];
        else if (n < 512) w = iW[d*256 + (n-256)];
        else if (n < 576) w = vW[d*64 + (n-512)];
        else if (n < 640) w = kW[d*64 + (n-576)];
        else if (n < 704) w = qW[d*64 + (n-640)];
        g_W1[idx] = tfr(w);
        if (idx < N1) {
            float b = 0.f;
            if      (idx < 256) b = gb[idx];
            else if (idx < 512) b = ib[idx-256];
            else if (idx < 576) b = vb[idx-512];
            else if (idx < 640) b = kb[idx-576];
            else if (idx < 704) b = qb[idx-640];
            g_b1[idx] = b;
        }
    } else if (bid < 2176) {
        int idx = (bid-1536)*256 + threadIdx.x;
        int r = idx / DD, c = idx % DD;
        g_W2[idx] = tfr((r < 256) ? oW[r*DD + c] : pW[(r-256)*DD + c]);
        if (idx < DD) g_b2[idx] = ob[idx] + pb[idx];
    } else {
        int i = threadIdx.x;
        if (i < ODIM) {
            float d = sigm_acc(op_decay[i]);
            float p = 1.f;
            for (int e = 0; e <= 64; e++) { g_pw[e*ODIM + i] = p; p *= d; }
        }
    }
}

// ---------------- tf32 tensor-core GEMM, 128x64 tile, BK=32, 3 CTAs/SM ----------------
#define AST2 36
#define BSTR3 72
#define A_BUF_F (128*AST2)          // 4608 floats per buffer
#define B_BUF_F (32*BSTR3)          // 2304 floats per buffer
#define GEMM_SMEM ((2*A_BUF_F + 2*B_BUF_F)*4)   // 55296 bytes

__device__ __forceinline__ void mma_tf32(float* c, const unsigned* a, const unsigned* b){
    asm volatile(
      "mma.sync.aligned.m16n8k8.row.col.f32.tf32.tf32.f32 "
      "{%0,%1,%2,%3}, {%4,%5,%6,%7}, {%8,%9}, {%0,%1,%2,%3};\n"
      : "+f"(c[0]), "+f"(c[1]), "+f"(c[2]), "+f"(c[3])
      : "r"(a[0]), "r"(a[1]), "r"(a[2]), "r"(a[3]), "r"(b[0]), "r"(b[1]));
}
__device__ __forceinline__ void cpa16(void* dst, const void* src){
    unsigned d = (unsigned)__cvta_generic_to_shared(dst);
    asm volatile("cp.async.cg.shared.global [%0], [%1], 16;" :: "r"(d), "l"(src));
}

__global__ void __launch_bounds__(256,3) gemm_tf32(
    const float* __restrict__ A, int lda,
    const float* __restrict__ Bw, int ldb,
    const float* __restrict__ bias,
    const float* __restrict__ addsrc, int ldadd,
    float* __restrict__ C, int ldc, int K)
{
    extern __shared__ float sm[];
    // layout: As[2][128][36] | Bs[2][32][72]

    int tid  = threadIdx.x;
    int lane = tid & 31, warp = tid >> 5;
    int wm = (warp >> 1) * 32;      // 4 M-warps: 0,32,64,96
    int wn = (warp & 1) * 32;       // 2 N-warps: 0,32
    int lr = lane >> 2;
    int lc = lane & 3;

    size_t rowBase = (size_t)blockIdx.y * 128;
    int colBase = blockIdx.x * 64;

    // A: 1024 16B-chunks per tile (4/thread); B: 512 chunks (2/thread)
    float acc[2][4][4];
    #pragma unroll
    for (int i = 0; i < 2; i++)
        #pragma unroll
        for (int j = 0; j < 4; j++)
            #pragma unroll
            for (int u = 0; u < 4; u++) acc[i][j][u] = 0.f;

    int nIter = K / 32;

    auto loadTile = [&](float* Asb, float* Bsb, int k0){
        #pragma unroll
        for (int j = 0; j < 4; j++) {
            int ac = tid + j*256;
            int r = ac >> 3, kc = (ac & 7) * 4;
            cpa16(Asb + r*AST2 + kc, A + (rowBase + r)*lda + k0 + kc);
        }
        #pragma unroll
        for (int j = 0; j < 2; j++) {
            int ac = tid + j*256;
            int br = ac >> 4, bn = (ac & 15) * 4;
            cpa16(Bsb + br*BSTR3 + bn, Bw + (size_t)(k0+br)*ldb + colBase + bn);
        }
    };

    loadTile(sm, sm + 2*A_BUF_F, 0);
    asm volatile("cp.async.commit_group;");

    int buf = 0;
    for (int it = 0; it < nIter; it++) {
        asm volatile("cp.async.wait_group 0;");
        __syncthreads();

        if (it + 1 < nIter) {
            int nb = buf ^ 1;
            loadTile(sm + nb*A_BUF_F, sm + 2*A_BUF_F + nb*B_BUF_F, (it+1)*32);
            asm volatile("cp.async.commit_group;");
        }

        const float* Asb = sm + buf*A_BUF_F;
        const float* Bsb = sm + 2*A_BUF_F + buf*B_BUF_F;

        #pragma unroll
        for (int kk = 0; kk < 32; kk += 8) {
            unsigned af[2][4], bf[4][2];
            #pragma unroll
            for (int mt = 0; mt < 2; mt++) {
                int m0 = wm + mt*16 + lr;
                af[mt][0] = __float_as_uint(Asb[m0*AST2 + kk + lc]);
                af[mt][1] = __float_as_uint(Asb[(m0+8)*AST2 + kk + lc]);
                af[mt][2] = __float_as_uint(Asb[m0*AST2 + kk + lc + 4]);
                af[mt][3] = __float_as_uint(Asb[(m0+8)*AST2 + kk + lc + 4]);
            }
            #pragma unroll
            for (int nt = 0; nt < 4; nt++) {
                int n0 = wn + nt*8 + lr;
                bf[nt][0] = __float_as_uint(Bsb[(kk + lc)*BSTR3 + n0]);
                bf[nt][1] = __float_as_uint(Bsb[(kk + lc + 4)*BSTR3 + n0]);
            }
            #pragma unroll
            for (int mt = 0; mt < 2; mt++)
                #pragma unroll
                for (int nt = 0; nt < 4; nt++)
                    mma_tf32(acc[mt][nt], af[mt], bf[nt]);
        }
        buf ^= 1;
    }

    // epilogue
    #pragma unroll
    for (int mt = 0; mt < 2; mt++) {
        size_t row0 = rowBase + wm + mt*16 + lr;
        #pragma unroll
        for (int nt = 0; nt < 4; nt++) {
            int col = colBase + wn + nt*8 + lc*2;
            float b0 = bias[col], b1 = bias[col+1];
            float a00=0.f,a01=0.f,a10=0.f,a11=0.f;
            if (addsrc) {
                const float* p0 = addsrc + row0*(size_t)ldadd + col;
                const float* p1 = addsrc + (row0+8)*(size_t)ldadd + col;
                a00 = p0[0]; a01 = p0[1]; a10 = p1[0]; a11 = p1[1];
            }
            float2 r0 = make_float2(acc[mt][nt][0] + b0 + a00, acc[mt][nt][1] + b1 + a01);
            float2 r1 = make_float2(acc[mt][nt][2] + b0 + a10, acc[mt][nt][3] + b1 + a11);
            *(float2*)(C + row0*(size_t)ldc + col)     = r0;
            *(float2*)(C + (row0+8)*(size_t)ldc + col) = r1;
        }
    }
}

// ---------------- gated scan helpers ----------------
__device__ __forceinline__ void scan_step(float zg, float zi, float& rca, float& wb)
{
    float t = __expf(-zg);
    float rca_new = rca * (1.f + t);
    float c = zi * t * rca;
    if (rca_new > 1e8f) c = zi * t * rca * __fdividef(1e8f, rca_new);
    wb += c;
    rca = rca_new;
}

// ---------------- fused phase 1: scan_summ (blocks 0..511) | bind_chunksum (512..767) ----------------
__global__ void __launch_bounds__(256) phase1()
{
    __shared__ float Vs[CB*ODIM];
    __shared__ float Ks[CB*ODIM];
    int bid = blockIdx.x;
    int tid = threadIdx.x;
    if (bid < 512) {
        // scan_summ
        int b = bid >> 6, c = bid & 63;
        int sd = tid;
        const float* zp = g_Z + ((size_t)(b*TT + c*CHK))*N1 + sd;
        float rca = 1.f, wb = 0.f;
        #pragma unroll 8
        for (int k = 0; k < CHK; k++) {
            float zg = __ldg(zp);
            float zi = __ldg(zp + SDIM);
            scan_step(zg, zi, rca, wb);
            zp += N1;
        }
        g_sumAB[bid*SDIM + sd] = make_float2(__fdividef(1.f, rca), wb);
    } else {
        // bind_chunksum
        int bc = bid - 512;
        int b = bc >> 5, c = bc & 31;
        int j = tid >> 2, q0 = (tid & 3)*16;
        size_t zrow = ((size_t)(b*TT + c*CB + j))*N1;
        #pragma unroll
        for (int u = 0; u < 4; u++) {
            float4 vv = __ldg((const float4*)&g_Z[zrow + 512 + q0 + u*4]);
            float4 pp = __ldg((const float4*)&g_pw[(63-j)*ODIM + q0 + u*4]);
            vv.x *= pp.x; vv.y *= pp.y; vv.z *= pp.z; vv.w *= pp.w;
            *(float4*)&Vs[j*ODIM + q0 + u*4] = vv;
            float4 kk = __ldg((const float4*)&g_Z[zrow + 576 + q0 + u*4]);
            *(float4*)&Ks[j*ODIM + q0 + u*4] = kk;
        }
        __syncthreads();
        if (tid < 128) {
            int i = tid >> 2;
            int l0 = (tid & 3)*16;
            float acc0[16] = {}, acc1[16] = {};
            for (int jj = 0; jj < CB; jj++) {
                float v0 = Vs[jj*ODIM + i];
                float v1 = Vs[jj*ODIM + i + 32];
                #pragma unroll
                for (int u = 0; u < 16; u += 4) {
                    float4 k4 = *(const float4*)&Ks[jj*ODIM + l0 + u];
                    acc0[u+0] += v0*k4.x; acc0[u+1] += v0*k4.y;
                    acc0[u+2] += v0*k4.z; acc0[u+3] += v0*k4.w;
                    acc1[u+0] += v1*k4.x; acc1[u+1] += v1*k4.y;
                    acc1[u+2] += v1*k4.z; acc1[u+3] += v1*k4.w;
                }
            }
            size_t mb0 = ((size_t)(b*NCB + c))*ODIM*ODIM + i*ODIM + l0;
            size_t mb1 = mb0 + 32*ODIM;
            #pragma unroll
            for (int u = 0; u < 16; u += 4) {
                *(float4*)&g_Mc[mb0 + u] = make_float4(acc0[u], acc0[u+1], acc0[u+2], acc0[u+3]);
                *(float4*)&g_Mc[mb1 + u] = make_float4(acc1[u], acc1[u+1], acc1[u+2], acc1[u+3]);
            }
        }
    }
}

// ---------------- fused phase 2: scan_carry (blocks 0..7) | bind_carry (8..135) ----------------
__global__ void __launch_bounds__(256,1) phase2()
{
    int bid = blockIdx.x;
    int tid = threadIdx.x;
    if (bid < 8) {
        int b = bid;
        int sd = tid;
        float h = 0.f;
        #pragma unroll
        for (int t0 = 0; t0 < NCH; t0 += 16) {
            float2 ab[16];
            #pragma unroll
            for (int k = 0; k < 16; k++)
                ab[k] = __ldg(&g_sumAB[(b*NCH + t0 + k)*SDIM + sd]);
            float hp[16];
            #pragma unroll
            for (int k = 0; k < 16; k++) { hp[k] = h; h = ab[k].x*(h + ab[k].y); }
            #pragma unroll
            for (int k = 0; k < 16; k++)
                g_hpr[(b*NCH + t0 + k)*SDIM + sd] = hp[k];
        }
    } else {
        int gid = (bid - 8)*256 + tid;   // 0..32767
        int b = gid >> 12, e = gid & 4095, i = e >> 6;
        float p64 = __ldg(&g_pw[64*ODIM + i]);
        size_t base = (size_t)b*NCB*4096 + e;
        float m[NCB];
        #pragma unroll
        for (int c = 0; c < NCB; c++)
            m[c] = __ldg(&g_Mc[base + (size_t)c*4096]);
        float s = 0.f;
        #pragma unroll
        for (int c = 0; c < NCB; c++) {
            g_Sc[base + (size_t)c*4096] = s;
            s = p64*s + m[c];
        }
    }
}

// ---------------- scan_states ----------------
__global__ void scan_states()
{
    int bc = blockIdx.x;
    int b = bc >> 6, c = bc & 63;
    int sd = threadIdx.x;
    const float* zp = g_Z + ((size_t)(b*TT + c*CHK))*N1 + sd;
    float* op = g_A2 + ((size_t)(b*TT + c*CHK))*KC2 + sd;
    float h = g_hpr[bc*SDIM + sd];
    float rca = 1.f, wb = 0.f;
    #pragma unroll 8
    for (int k = 0; k < CHK; k++) {
        float zg = __ldg(zp);
        float zi = __ldg(zp + SDIM);
        scan_step(zg, zi, rca, wb);
        *op = tfr(__fdividef(h + wb, rca));
        zp += N1; op += KC2;
    }
}

// ---------------- bind_out (2x t-register-blocked) ----------------
__global__ void bind_out()
{
    extern __shared__ float sm[];
    float* Qs  = sm;            // [64][65]
    float* KT  = sm + 4160;     // [64][64]
    float* SV  = sm + 8256;     // [64][64]
    float* As  = sm + 12352;    // [64][65]
    float* pws = sm + 16512;    // [65][64]
    int b = blockIdx.x >> 5, c = blockIdx.x & 31;
    int tid = threadIdx.x;
    int t = tid >> 2, q0 = (tid & 3)*16;
    size_t zrow = ((size_t)(b*TT + c*CB + t))*N1;
    size_t srow = ((size_t)(b*NCB + c))*4096 + t*ODIM;
    #pragma unroll
    for (int u = 0; u < 4; u++) {
        float4 qv = __ldg((const float4*)&g_Z[zrow + 640 + q0 + u*4]);
        Qs[t*65 + q0+u*4+0] = qv.x; Qs[t*65 + q0+u*4+1] = qv.y;
        Qs[t*65 + q0+u*4+2] = qv.z; Qs[t*65 + q0+u*4+3] = qv.w;
        float4 kv = __ldg((const float4*)&g_Z[zrow + 576 + q0 + u*4]);
        KT[(q0+u*4+0)*ODIM + t] = kv.x; KT[(q0+u*4+1)*ODIM + t] = kv.y;
        KT[(q0+u*4+2)*ODIM + t] = kv.z; KT[(q0+u*4+3)*ODIM + t] = kv.w;
        float4 sv = __ldg((const float4*)&g_Sc[srow + q0 + u*4]);
        SV[(q0+u*4+0)*ODIM + t] = sv.x; SV[(q0+u*4+1)*ODIM + t] = sv.y;
        SV[(q0+u*4+2)*ODIM + t] = sv.z; SV[(q0+u*4+3)*ODIM + t] = sv.w;
    }
    for (int idx = tid; idx < 65*ODIM; idx += 256) pws[idx] = __ldg(&g_pw[idx]);
    __syncthreads();

    int t0 = (tid >> 2) & 31;
    float accA0[16], accA1[16], accC0[16], accC1[16];
    if (tid < 128) {
        #pragma unroll
        for (int u = 0; u < 16; u++) { accA0[u]=0.f; accA1[u]=0.f; accC0[u]=0.f; accC1[u]=0.f; }
        for (int l = 0; l < ODIM; l++) {
            float qa = Qs[t0*65 + l];
            float qb = Qs[(t0+32)*65 + l];
            #pragma unroll
            for (int u = 0; u < 16; u += 4) {
                float4 k4 = *(const float4*)&KT[l*ODIM + q0 + u];
                float4 s4 = *(const float4*)&SV[l*ODIM + q0 + u];
                accA0[u+0] += qa*k4.x; accA0[u+1] += qa*k4.y; accA0[u+2] += qa*k4.z; accA0[u+3] += qa*k4.w;
                accA1[u+0] += qb*k4.x; accA1[u+1] += qb*k4.y; accA1[u+2] += qb*k4.z; accA1[u+3] += qb*k4.w;
                accC0[u+0] += qa*s4.x; accC0[u+1] += qa*s4.y; accC0[u+2] += qa*s4.z; accC0[u+3] += qa*s4.w;
                accC1[u+0] += qb*s4.x; accC1[u+1] += qb*s4.y; accC1[u+2] += qb*s4.z; accC1[u+3] += qb*s4.w;
            }
        }
    }
    __syncthreads();
    if (tid < 128) {
        #pragma unroll
        for (int u = 0; u < 16; u++) {
            As[t0*65 + q0 + u]      = accA0[u];
            As[(t0+32)*65 + q0 + u] = accA1[u];
        }
        #pragma unroll
        for (int u = 0; u < 16; u += 4) {
            *(float4*)&KT[t0*ODIM + q0 + u]      = make_float4(accC0[u], accC0[u+1], accC0[u+2], accC0[u+3]);
            *(float4*)&KT[(t0+32)*ODIM + q0 + u] = make_float4(accC1[u], accC1[u+1], accC1[u+2], accC1[u+3]);
        }
    }
    #pragma unroll
    for (int u = 0; u < 4; u++) {
        float4 vv = __ldg((const float4*)&g_Z[zrow + 512 + q0 + u*4]);
        *(float4*)&SV[t*ODIM + q0 + u*4] = vv;
    }
    __syncthreads();

    if (tid < 128) {
        int ta = t0, tb = t0 + 32;
        float o0[16], o1[16];
        #pragma unroll
        for (int u = 0; u < 16; u++) {
            o0[u] = pws[(ta+1)*ODIM + q0 + u] * KT[ta*ODIM + q0 + u];
            o1[u] = pws[(tb+1)*ODIM + q0 + u] * KT[tb*ODIM + q0 + u];
        }
        for (int j = 0; j <= tb; j++) {
            float a1 = As[tb*65 + j];
            int d1 = tb - j;
            bool inA = (j <= ta);
            float a0 = inA ? As[ta*65 + j] : 0.f;
            int d0 = inA ? (ta - j) : 0;
            #pragma unroll
            for (int u = 0; u < 16; u += 4) {
                float4 v4  = *(const float4*)&SV[j*ODIM + q0 + u];
                float4 p1v = *(const float4*)&pws[d1*ODIM + q0 + u];
                o1[u+0] += a1*p1v.x*v4.x; o1[u+1] += a1*p1v.y*v4.y;
                o1[u+2] += a1*p1v.z*v4.z; o1[u+3] += a1*p1v.w*v4.w;
                if (inA) {
                    float4 p0v = *(const float4*)&pws[d0*ODIM + q0 + u];
                    o0[u+0] += a0*p0v.x*v4.x; o0[u+1] += a0*p0v.y*v4.y;
                    o0[u+2] += a0*p0v.z*v4.z; o0[u+3] += a0*p0v.w*v4.w;
                }
            }
        }
        size_t orow0 = ((size_t)(b*TT + c*CB + ta))*KC2 + SDIM + q0;
        size_t orow1 = ((size_t)(b*TT + c*CB + tb))*KC2 + SDIM + q0;
        #pragma unroll
        for (int u = 0; u < 16; u += 4) {
            *(float4*)&g_A2[orow0 + u] = make_float4(tfr(o0[u]), tfr(o0[u+1]), tfr(o0[u+2]), tfr(o0[u+3]));
            *(float4*)&g_A2[orow1 + u] = make_float4(tfr(o1[u]), tfr(o1[u+1]), tfr(o1[u+2]), tfr(o1[u+3]));
        }
    }
}

// ---------------- layernorm: warp per row ----------------
__global__ void ln_kernel(const float* __restrict__ lng, const float* __restrict__ lnb,
                          float* __restrict__ out)
{
    int row = blockIdx.x*8 + (threadIdx.x >> 5);
    int lane = threadIdx.x & 31;
    const float4* y4 = (const float4*)(g_Y + (size_t)row*DD);
    float4 v[4];
    float s = 0.f, s2 = 0.f;
    #pragma unroll
    for (int u = 0; u < 4; u++) {
        v[u] = __ldg(y4 + lane + u*32);
        s  += v[u].x + v[u].y + v[u].z + v[u].w;
        s2 += v[u].x*v[u].x + v[u].y*v[u].y + v[u].z*v[u].z + v[u].w*v[u].w;
    }
    #pragma unroll
    for (int off = 16; off; off >>= 1) {
        s  += __shfl_xor_sync(0xffffffffu, s,  off);
        s2 += __shfl_xor_sync(0xffffffffu, s2, off);
    }
    float mu  = s * (1.f/512.f);
    float var = s2 * (1.f/512.f) - mu*mu;
    float inv = rsqrtf(var + 1e-5f);
    float4* o4 = (float4*)(out + (size_t)row*DD);
    const float4* g4 = (const float4*)lng;
    const float4* b4 = (const float4*)lnb;
    #pragma unroll
    for (int u = 0; u < 4; u++) {
        float4 gg = __ldg(g4 + lane + u*32);
        float4 bb = __ldg(b4 + lane + u*32);
        float4 r;
        r.x = (v[u].x - mu)*inv*gg.x + bb.x;
        r.y = (v[u].y - mu)*inv*gg.y + bb.y;
        r.z = (v[u].z - mu)*inv*gg.z + bb.z;
        r.w = (v[u].w - mu)*inv*gg.w + bb.w;
        o4[lane + u*32] = r;
    }
}

// ---------------- host launch ----------------
extern "C" void kernel_launch(void* const* d_in, const int* in_sizes, int n_in,
                              void* d_out, int out_size)
{
    const float* x       = (const float*)d_in[0];
    const float* gate_W  = (const float*)d_in[1];
    const float* gate_b  = (const float*)d_in[2];
    const float* in_W    = (const float*)d_in[3];
    const float* in_b    = (const float*)d_in[4];
    const float* out_W   = (const float*)d_in[5];
    const float* out_b   = (const float*)d_in[6];
    const float* opv_W   = (const float*)d_in[7];
    const float* opv_b   = (const float*)d_in[8];
    const float* opk_W   = (const float*)d_in[9];
    const float* opk_b   = (const float*)d_in[10];
    const float* opq_W   = (const float*)d_in[11];
    const float* opq_b   = (const float*)d_in[12];
    const float* op_decay= (const float*)d_in[13];
    const float* opout_W = (const float*)d_in[14];
    const float* opout_b = (const float*)d_in[15];
    const float* ln_g    = (const float*)d_in[16];
    const float* ln_b    = (const float*)d_in[17];
    float* out = (float*)d_out;

    void *pW1, *pb1, *pZ, *pW2, *pb2, *pA2, *pY;
    cudaGetSymbolAddress(&pW1, g_W1);
    cudaGetSymbolAddress(&pb1, g_b1);
    cudaGetSymbolAddress(&pZ,  g_Z);
    cudaGetSymbolAddress(&pW2, g_W2);
    cudaGetSymbolAddress(&pb2, g_b2);
    cudaGetSymbolAddress(&pA2, g_A2);
    cudaGetSymbolAddress(&pY,  g_Y);

    cudaFuncSetAttribute(gemm_tf32, cudaFuncAttributeMaxDynamicSharedMemorySize, GEMM_SMEM);
    cudaFuncSetAttribute(bind_out, cudaFuncAttributeMaxDynamicSharedMemorySize, 20672*4);

    // prep (fused)
    pack_all<<<2177, 256>>>(gate_W, gate_b, in_W, in_b,
                            opv_W, opv_b, opk_W, opk_b, opq_W, opq_b,
                            out_W, out_b, opout_W, opout_b, op_decay);

    // GEMM-1: Z = x @ W1 + b1
    gemm_tf32<<<dim3(N1/64, MM/128), 256, GEMM_SMEM>>>(
        x, DD, (const float*)pW1, N1, (const float*)pb1,
        nullptr, 0, (float*)pZ, N1, DD);

    // phase 1: gated-scan summaries | binding chunk sums
    phase1<<<768, 256>>>();
    // phase 2: gated-scan carry | binding carry
    phase2<<<136, 256>>>();
    // phase 3
    scan_states<<<BQ*NCH, SDIM>>>();
    bind_out<<<BQ*NCB, 256, 20672*4>>>();

    // GEMM-2: Y = A2 @ W2 + b2 + x
    gemm_tf32<<<dim3(DD/64, MM/128), 256, GEMM_SMEM>>>(
        (const float*)pA2, KC2, (const float*)pW2, DD, (const float*)pb2,
        x, DD, (float*)pY, DD, KC2);

    // layernorm -> out
    ln_kernel<<<MM/8, 256>>>(ln_g, ln_b, out);
}